// round 4
// baseline (speedup 1.0000x reference)
#include <cuda_runtime.h>
#include <cuda_bf16.h>
#include <cstdint>

#define Bn 2
#define Cn 31
#define Dn 7
#define Hn 192
#define Wn 192
#define HWn (Hn * Wn)          // 36864
#define KP 70                  // KAN_PARAMS
#define COEF_LEN 56
#define NB 8                   // N_BASIS

// ---------------- scratch (no allocations allowed) ----------------
__device__ float g_ctx[Bn * Cn * HWn];   // [B, C, H, W]   ~9.1 MB
__device__ float g_wts[Bn * KP * HWn];   // [B, 70, H, W]  ~20.6 MB

// ---------------- packed f32x2 helpers (sm_103a FFMA2) ----------------
__device__ __forceinline__ unsigned long long fma2(unsigned long long a,
                                                   unsigned long long b,
                                                   unsigned long long c) {
    unsigned long long d;
    asm("fma.rn.f32x2 %0, %1, %2, %3;" : "=l"(d) : "l"(a), "l"(b), "l"(c));
    return d;
}
__device__ __forceinline__ unsigned long long pack2(float lo, float hi) {
    unsigned long long d;
    asm("mov.b64 %0, {%1, %2};" : "=l"(d) : "f"(lo), "f"(hi));
    return d;
}
__device__ __forceinline__ void unpack2(unsigned long long v, float& lo, float& hi) {
    asm("mov.b64 {%0, %1}, %2;" : "=f"(lo), "=f"(hi) : "l"(v));
}

// ---------------- kernel 1: mean over D (float4) ----------------
__global__ void mean_kernel(const float* __restrict__ x) {
    int i = blockIdx.x * 256 + threadIdx.x;        // float4 index
    const int HW4 = HWn / 4;                       // 9216
    int hw4 = i % HW4;
    int bc  = i / HW4;
    const float4* p = (const float4*)(x + (size_t)bc * Dn * HWn) + hw4;
    float4 s = make_float4(0.f, 0.f, 0.f, 0.f);
#pragma unroll
    for (int d = 0; d < Dn; d++) {
        float4 v = p[(size_t)d * HW4];
        s.x += v.x; s.y += v.y; s.z += v.z; s.w += v.w;
    }
    const float inv7 = 1.0f / 7.0f;
    s.x *= inv7; s.y *= inv7; s.z *= inv7; s.w *= inv7;
    ((float4*)g_ctx)[i] = s;
}

// ---------------- kernel 2: 3x3 SAME conv 31->70 + bias (f32x2) ----------------
// block 256 = 32 thread-cols x 8 thread-rows; thread tile 2x2 pixels x 10 couts.
// Output tile 64x16. grid = (3, 12, B*7). Channel staging chunked (16+15).
// Staging is fully div-free: thread -> (row=tid>>6, col=tid&63).
#define TILE_W 64
#define TILE_H 16
#define TC 10
#define CI_CHUNK 16
#define S_TILE_FLOATS (CI_CHUNK * 18 * 66)          // 19008 floats = 76032 B
#define S_W_PAIRS     (Cn * 9 * TC)                 // 2790 pairs   = 22320 B
#define CONV_SMEM_BYTES (S_TILE_FLOATS * 4 + S_W_PAIRS * 8)

__global__ void __launch_bounds__(256, 2)
conv_kernel(const float* __restrict__ gw, const float* __restrict__ gb) {
    extern __shared__ char smem_raw[];
    float* s_tile = (float*)smem_raw;                                    // [ci_chunk][18][66]
    unsigned long long* s_wd = (unsigned long long*)(smem_raw + S_TILE_FLOATS * 4);

    int tid = threadIdx.x;
    int bz = blockIdx.z;
    int cochunk = bz % 7;
    int b = bz / 7;

    int ox = blockIdx.x * TILE_W - 1;
    int oy = blockIdx.y * TILE_H - 1;
    const float* ctx = g_ctx + (size_t)b * Cn * HWn;

    // stage duplicated weight pairs for this cout chunk (once)
    for (int idx = tid; idx < S_W_PAIRS; idx += 256) {
        int j = idx % TC;
        int r = idx / TC;                 // ci*9 + kk
        int ci = r / 9, kk = r % 9;
        int co = cochunk * TC + j;
        float w = gw[((size_t)co * Cn + ci) * 9 + kk];
        s_wd[idx] = pack2(w, w);
    }

    // div-free staging mapping
    int trow = tid >> 6;                  // 0..3
    int tcol = tid & 63;                  // 0..63
    int gx_main = ox + tcol;
    int gx_tail = ox + 64 + tcol;         // used when tcol < 2
    bool vx_main = (gx_main >= 0) && (gx_main < Wn);
    bool vx_tail = (tcol < 2) && (gx_tail < Wn);   // gx_tail >= 63 always

    int lx = (tid & 31) * 2;              // 0..62
    int ly = (tid >> 5) * 2;              // 0..14

    unsigned long long acc[2][TC];
#pragma unroll
    for (int p = 0; p < 2; p++)
#pragma unroll
        for (int j = 0; j < TC; j++) acc[p][j] = 0ull;

    for (int c0 = 0; c0 < Cn; c0 += CI_CHUNK) {
        int nc = (Cn - c0 < CI_CHUNK) ? (Cn - c0) : CI_CHUNK;

        // stage input tile chunk (with halo, zero-padded), no int div
#pragma unroll 1
        for (int ci = 0; ci < nc; ci++) {
            const float* src = ctx + (size_t)(c0 + ci) * HWn;
            float* dst = s_tile + ci * (18 * 66);
#pragma unroll
            for (int yb = 0; yb < 20; yb += 4) {
                int y = yb + trow;
                if (y < 18) {
                    int gy = oy + y;
                    bool vy = (gy >= 0) && (gy < Hn);
                    const float* srow = src + gy * Wn;
                    dst[y * 66 + tcol] = (vy && vx_main) ? srow[gx_main] : 0.f;
                    if (tcol < 2)
                        dst[y * 66 + 64 + tcol] = (vy && vx_tail) ? srow[gx_tail] : 0.f;
                }
            }
        }
        __syncthreads();

#pragma unroll 1
        for (int cl = 0; cl < nc; cl++) {
            const float* t = s_tile + cl * (18 * 66);
            int ci_g = c0 + cl;

#pragma unroll
            for (int ky = 0; ky < 3; ky++) {
                float2 a0 = *(const float2*)(t + (ly + ky) * 66 + lx);
                float2 a1 = *(const float2*)(t + (ly + ky) * 66 + lx + 2);
                float2 b0 = *(const float2*)(t + (ly + ky + 1) * 66 + lx);
                float2 b1 = *(const float2*)(t + (ly + ky + 1) * 66 + lx + 2);
                unsigned long long pa[3], pb[3];
                pa[0] = pack2(a0.x, a0.y); pa[1] = pack2(a0.y, a1.x); pa[2] = pack2(a1.x, a1.y);
                pb[0] = pack2(b0.x, b0.y); pb[1] = pack2(b0.y, b1.x); pb[2] = pack2(b1.x, b1.y);

#pragma unroll
                for (int kx = 0; kx < 3; kx++) {
                    const ulonglong2* wrow =
                        (const ulonglong2*)(s_wd + (size_t)(ci_g * 9 + ky * 3 + kx) * TC);
                    ulonglong2 w01 = wrow[0];
                    ulonglong2 w23 = wrow[1];
                    ulonglong2 w45 = wrow[2];
                    ulonglong2 w67 = wrow[3];
                    ulonglong2 w89 = wrow[4];
                    unsigned long long wv[TC] = {w01.x, w01.y, w23.x, w23.y, w45.x,
                                                 w45.y, w67.x, w67.y, w89.x, w89.y};
#pragma unroll
                    for (int j = 0; j < TC; j++) {
                        acc[0][j] = fma2(pa[kx], wv[j], acc[0][j]);
                        acc[1][j] = fma2(pb[kx], wv[j], acc[1][j]);
                    }
                }
            }
        }
        __syncthreads();
    }

    int gx = blockIdx.x * TILE_W + lx;
    float* outp = g_wts + (size_t)b * KP * HWn;
#pragma unroll
    for (int j = 0; j < TC; j++) {
        int co = cochunk * TC + j;
        float bias = __ldg(gb + co);
#pragma unroll
        for (int p = 0; p < 2; p++) {
            int gy = blockIdx.y * TILE_H + ly + p;
            float lo, hi;
            unpack2(acc[p][j], lo, hi);
            *(float2*)(outp + (size_t)co * HWn + gy * Wn + gx) =
                make_float2(lo + bias, hi + bias);
        }
    }
}

// ---------------- kernel 3: fused branch-free bspline + silu ----------------
// Transposed coef table: ws_t[slot][256 px]; every thread accesses column tid
// -> bank = tid mod 32 for ANY dynamic slot -> zero conflicts on write & gather.
#define KAN_SLOTS 98                           // 7 d * 14 slots (3 zero-pad each side)
#define KAN_SMEM_BYTES (KAN_SLOTS * 256 * 4)   // 100,352 B

__global__ void __launch_bounds__(256, 2)
kan_kernel(const float* __restrict__ xin, float* __restrict__ out) {
    extern __shared__ float smem[];
    int tid = threadIdx.x;
    int b = blockIdx.y;
    int p = blockIdx.x * 256 + tid;

    float* col = smem + tid;                       // element (slot s, px tid) at s*256+tid
    const float* wbase = g_wts + (size_t)b * KP * HWn + p;

    // zero pads
#pragma unroll
    for (int d = 0; d < Dn; d++) {
        col[(d * 14 + 0) * 256]  = 0.f; col[(d * 14 + 1) * 256]  = 0.f; col[(d * 14 + 2) * 256]  = 0.f;
        col[(d * 14 + 11) * 256] = 0.f; col[(d * 14 + 12) * 256] = 0.f; col[(d * 14 + 13) * 256] = 0.f;
    }
    // coefficients (coalesced gmem loads; own column -> no sync needed)
#pragma unroll
    for (int k = 0; k < COEF_LEN; k++) {
        int d = k >> 3, g = k & 7;
        col[(d * 14 + 3 + g) * 256] = wbase[(size_t)k * HWn];
    }

    float uw[Dn], rw[Dn];
#pragma unroll
    for (int d = 0; d < Dn; d++) {
        uw[d] = wbase[(size_t)(COEF_LEN + d) * HWn] * (1.0f / 6.0f);  // fold spline 1/6
        rw[d] = wbase[(size_t)(COEF_LEN + Dn + d) * HWn];
    }

    const float* xb = xin + (size_t)b * Cn * Dn * HWn + p;
    float* ob = out + (size_t)b * Cn * HWn + p;

    for (int c = 0; c < Cn; c++) {
        float xv[Dn];
#pragma unroll
        for (int d = 0; d < Dn; d++)
            xv[d] = xb[(size_t)(c * Dn + d) * HWn];

        float acc = 0.f;
#pragma unroll
        for (int d = 0; d < Dn; d++) {
            float x = xv[d];
            // uniform cubic B-spline on knots -2.2 + 0.4k; 11 valid intervals
            float xs = fmaf(x, 2.5f, 5.5f);
            float jf = floorf(xs);
            int j = (int)jf;
            float t = xs - jf;
            unsigned ju = (unsigned)j;
            float vm = (ju <= 10u) ? 1.f : 0.f;
            int jc = (ju <= 10u) ? j : 0;

            float t2 = t * t;
            float t3 = t2 * t;
            float omt = 1.f - t;
            float u0 = omt * omt * omt;                       // 1/6 folded into uw
            float u1 = 3.f * t3 - 6.f * t2 + 4.f;
            float u2 = -3.f * t3 + 3.f * t2 + 3.f * t + 1.f;
            float u3 = t3;

            const float* cf = col + (d * 14 + jc) * 256;      // conflict-free gather
            float sa = u0 * cf[0];
            sa = fmaf(u1, cf[256], sa);
            sa = fmaf(u2, cf[512], sa);
            sa = fmaf(u3, cf[768], sa);
            acc = fmaf(sa * vm, uw[d], acc);

            float sig = 1.f / (1.f + __expf(-x));
            acc = fmaf(x * sig, rw[d], acc);
        }
        ob[(size_t)c * HWn] = acc;
    }
}

// ---------------- launch ----------------
extern "C" void kernel_launch(void* const* d_in, const int* in_sizes, int n_in,
                              void* d_out, int out_size) {
    const float* x  = (const float*)d_in[0];   // windowed_x [2,31,7,192,192]
    const float* gw = (const float*)d_in[1];   // gen_w [70,31,3,3]
    const float* gb = (const float*)d_in[2];   // gen_b [70]
    float* out = (float*)d_out;                // [2,31,192,192]

    cudaFuncSetAttribute(conv_kernel, cudaFuncAttributeMaxDynamicSharedMemorySize, CONV_SMEM_BYTES);
    cudaFuncSetAttribute(kan_kernel,  cudaFuncAttributeMaxDynamicSharedMemorySize, KAN_SMEM_BYTES);

    mean_kernel<<<(Bn * Cn * HWn / 4) / 256, 256>>>(x);
    conv_kernel<<<dim3(Wn / TILE_W, Hn / TILE_H, Bn * 7), 256, CONV_SMEM_BYTES>>>(gw, gb);
    kan_kernel<<<dim3(HWn / 256, Bn), 256, KAN_SMEM_BYTES>>>(x, out);
}

// round 5
// speedup vs baseline: 1.3330x; 1.3330x over previous
#include <cuda_runtime.h>
#include <cuda_bf16.h>
#include <cstdint>

#define Bn 2
#define Cn 31
#define Dn 7
#define Hn 192
#define Wn 192
#define HWn (Hn * Wn)          // 36864
#define KP 70                  // KAN_PARAMS
#define COEF_LEN 56
#define NB 8                   // N_BASIS

// ---------------- scratch (no allocations allowed) ----------------
__device__ float g_ctx[Bn * Cn * HWn];   // [B, C, H, W]   ~9.1 MB
__device__ float g_wts[Bn * KP * HWn];   // [B, 70, H, W]  ~20.6 MB

// ---------------- packed f32x2 helpers (sm_103a FFMA2) ----------------
__device__ __forceinline__ unsigned long long fma2(unsigned long long a,
                                                   unsigned long long b,
                                                   unsigned long long c) {
    unsigned long long d;
    asm("fma.rn.f32x2 %0, %1, %2, %3;" : "=l"(d) : "l"(a), "l"(b), "l"(c));
    return d;
}
__device__ __forceinline__ unsigned long long pack2(float lo, float hi) {
    unsigned long long d;
    asm("mov.b64 %0, {%1, %2};" : "=l"(d) : "f"(lo), "f"(hi));
    return d;
}
__device__ __forceinline__ void unpack2(unsigned long long v, float& lo, float& hi) {
    asm("mov.b64 {%0, %1}, %2;" : "=f"(lo), "=f"(hi) : "l"(v));
}

// ---------------- kernel 1: mean over D (2x float4 per thread) ----------------
// B*C*HW/4 = 571,392 float4; 2 per thread -> 285,696 threads = 1116 blocks x 256
__global__ void mean_kernel(const float* __restrict__ x) {
    const int HW4 = HWn / 4;                       // 9216
    int i0 = (blockIdx.x * 256 + threadIdx.x) * 2; // first float4 index
#pragma unroll
    for (int u = 0; u < 2; u++) {
        int i = i0 + u;
        int hw4 = i % HW4;
        int bc  = i / HW4;
        const float4* p = (const float4*)(x + (size_t)bc * Dn * HWn) + hw4;
        float4 s = make_float4(0.f, 0.f, 0.f, 0.f);
#pragma unroll
        for (int d = 0; d < Dn; d++) {
            float4 v = p[(size_t)d * HW4];
            s.x += v.x; s.y += v.y; s.z += v.z; s.w += v.w;
        }
        const float inv7 = 1.0f / 7.0f;
        s.x *= inv7; s.y *= inv7; s.z *= inv7; s.w *= inv7;
        ((float4*)g_ctx)[i] = s;
    }
}

// ---------------- kernel 2: 3x3 SAME conv 31->70 + bias (f32x2) ----------------
// block 256 = 32 thread-cols x 8 thread-rows; thread tile 2x2 pixels x 10 couts.
// Output tile 64x16. grid = (3, 12, B*7). Channel staging chunked (16+15).
#define TILE_W 64
#define TILE_H 16
#define TC 10
#define CI_CHUNK 16
#define S_TILE_FLOATS (CI_CHUNK * 18 * 66)          // 19008 floats = 76032 B
#define S_W_PAIRS     (Cn * 9 * TC)                 // 2790 pairs   = 22320 B
#define CONV_SMEM_BYTES (S_TILE_FLOATS * 4 + S_W_PAIRS * 8)

__global__ void __launch_bounds__(256, 2)
conv_kernel(const float* __restrict__ gw, const float* __restrict__ gb) {
    extern __shared__ char smem_raw[];
    float* s_tile = (float*)smem_raw;                                    // [ci_chunk][18][66]
    unsigned long long* s_wd = (unsigned long long*)(smem_raw + S_TILE_FLOATS * 4);

    int tid = threadIdx.x;
    int bz = blockIdx.z;
    int cochunk = bz % 7;
    int b = bz / 7;

    int ox = blockIdx.x * TILE_W - 1;
    int oy = blockIdx.y * TILE_H - 1;
    const float* ctx = g_ctx + (size_t)b * Cn * HWn;

    // stage duplicated weight pairs for this cout chunk (once)
    for (int idx = tid; idx < S_W_PAIRS; idx += 256) {
        int j = idx % TC;
        int r = idx / TC;                 // ci*9 + kk
        int ci = r / 9, kk = r % 9;
        int co = cochunk * TC + j;
        float w = gw[((size_t)co * Cn + ci) * 9 + kk];
        s_wd[idx] = pack2(w, w);
    }

    int lx = (tid & 31) * 2;              // 0..62
    int ly = (tid >> 5) * 2;              // 0..14

    unsigned long long acc[2][TC];
#pragma unroll
    for (int p = 0; p < 2; p++)
#pragma unroll
        for (int j = 0; j < TC; j++) acc[p][j] = 0ull;

    for (int c0 = 0; c0 < Cn; c0 += CI_CHUNK) {
        int nc = (Cn - c0 < CI_CHUNK) ? (Cn - c0) : CI_CHUNK;
        // stage input tile chunk (with halo, zero-padded); divisors are constants
        for (int idx = tid; idx < nc * 18 * 66; idx += 256) {
            int ci = idx / (18 * 66);
            int r  = idx % (18 * 66);
            int y = r / 66, xx = r % 66;
            int gy = oy + y, gx = ox + xx;
            float v = 0.f;
            if (gy >= 0 && gy < Hn && gx >= 0 && gx < Wn)
                v = ctx[(size_t)(c0 + ci) * HWn + gy * Wn + gx];
            s_tile[idx] = v;
        }
        __syncthreads();

#pragma unroll 1
        for (int cl = 0; cl < nc; cl++) {
            const float* t = s_tile + cl * (18 * 66);
            int ci_g = c0 + cl;

            // preload all 4 input rows as aligned u64 pairs (batched -> MLP 8)
            unsigned long long rp[4][2];
#pragma unroll
            for (int r = 0; r < 4; r++) {
                rp[r][0] = *(const unsigned long long*)(t + (ly + r) * 66 + lx);
                rp[r][1] = *(const unsigned long long*)(t + (ly + r) * 66 + lx + 2);
            }
            // straddle packs (cols lx+1, lx+2) per row
            unsigned long long rs[4];
#pragma unroll
            for (int r = 0; r < 4; r++) {
                float lo0, hi0, lo1, hi1;
                unpack2(rp[r][0], lo0, hi0);
                unpack2(rp[r][1], lo1, hi1);
                rs[r] = pack2(hi0, lo1);
            }

#pragma unroll
            for (int ky = 0; ky < 3; ky++) {
                unsigned long long pa[3] = { rp[ky][0],     rs[ky],     rp[ky][1] };
                unsigned long long pb[3] = { rp[ky + 1][0], rs[ky + 1], rp[ky + 1][1] };

#pragma unroll
                for (int kx = 0; kx < 3; kx++) {
                    const ulonglong2* wrow =
                        (const ulonglong2*)(s_wd + (size_t)(ci_g * 9 + ky * 3 + kx) * TC);
                    ulonglong2 w01 = wrow[0];
                    ulonglong2 w23 = wrow[1];
                    ulonglong2 w45 = wrow[2];
                    ulonglong2 w67 = wrow[3];
                    ulonglong2 w89 = wrow[4];
                    unsigned long long wv[TC] = {w01.x, w01.y, w23.x, w23.y, w45.x,
                                                 w45.y, w67.x, w67.y, w89.x, w89.y};
#pragma unroll
                    for (int j = 0; j < TC; j++) {
                        acc[0][j] = fma2(pa[kx], wv[j], acc[0][j]);
                        acc[1][j] = fma2(pb[kx], wv[j], acc[1][j]);
                    }
                }
            }
        }
        __syncthreads();
    }

    int gx = blockIdx.x * TILE_W + lx;
    float* outp = g_wts + (size_t)b * KP * HWn;
#pragma unroll
    for (int j = 0; j < TC; j++) {
        int co = cochunk * TC + j;
        float bias = __ldg(gb + co);
#pragma unroll
        for (int p = 0; p < 2; p++) {
            int gy = blockIdx.y * TILE_H + ly + p;
            float lo, hi;
            unpack2(acc[p][j], lo, hi);
            *(float2*)(outp + (size_t)co * HWn + gy * Wn + gx) =
                make_float2(lo + bias, hi + bias);
        }
    }
}

// ---------------- kernel 3: fused branch-free bspline + silu (round-3 layout) ----------------
#define KAN_ROW 99
#define KAN_SMEM_BYTES (256 * KAN_ROW * 4)

__global__ void __launch_bounds__(256, 2)
kan_kernel(const float* __restrict__ xin, float* __restrict__ out) {
    extern __shared__ float smem[];
    int tid = threadIdx.x;
    int b = blockIdx.y;
    int p = blockIdx.x * 256 + tid;

    float* ws = smem + tid * KAN_ROW;
    const float* wbase = g_wts + (size_t)b * KP * HWn + p;

    // zero pads (3 each side of the 8 real coefficients per d)
#pragma unroll
    for (int d = 0; d < Dn; d++) {
        ws[d * 14 + 0]  = 0.f; ws[d * 14 + 1]  = 0.f; ws[d * 14 + 2]  = 0.f;
        ws[d * 14 + 11] = 0.f; ws[d * 14 + 12] = 0.f; ws[d * 14 + 13] = 0.f;
    }
#pragma unroll
    for (int k = 0; k < COEF_LEN; k++) {
        int d = k >> 3, g = k & 7;
        ws[d * 14 + 3 + g] = wbase[(size_t)k * HWn];
    }

    float uw[Dn], rw[Dn];
#pragma unroll
    for (int d = 0; d < Dn; d++) {
        uw[d] = wbase[(size_t)(COEF_LEN + d) * HWn] * (1.0f / 6.0f);  // fold spline 1/6
        rw[d] = wbase[(size_t)(COEF_LEN + Dn + d) * HWn];
    }

    const float* xb = xin + (size_t)b * Cn * Dn * HWn + p;
    float* ob = out + (size_t)b * Cn * HWn + p;

    for (int c = 0; c < Cn; c++) {
        float xv[Dn];
#pragma unroll
        for (int d = 0; d < Dn; d++)
            xv[d] = xb[(size_t)(c * Dn + d) * HWn];

        float acc = 0.f;
#pragma unroll
        for (int d = 0; d < Dn; d++) {
            float x = xv[d];
            // uniform cubic B-spline on knots -2.2 + 0.4k; 11 valid intervals
            float xs = fmaf(x, 2.5f, 5.5f);
            float jf = floorf(xs);
            int j = (int)jf;
            float t = xs - jf;
            unsigned ju = (unsigned)j;
            float vm = (ju <= 10u) ? 1.f : 0.f;
            int jc = (ju <= 10u) ? j : 0;

            float t2 = t * t;
            float t3 = t2 * t;
            float omt = 1.f - t;
            float u0 = omt * omt * omt;                       // 1/6 folded into uw
            float u1 = 3.f * t3 - 6.f * t2 + 4.f;
            float u2 = -3.f * t3 + 3.f * t2 + 3.f * t + 1.f;
            float u3 = t3;

            const float* cf = ws + d * 14 + jc;
            float sa = u0 * cf[0];
            sa = fmaf(u1, cf[1], sa);
            sa = fmaf(u2, cf[2], sa);
            sa = fmaf(u3, cf[3], sa);
            acc = fmaf(sa * vm, uw[d], acc);

            float sig = 1.f / (1.f + __expf(-x));
            acc = fmaf(x * sig, rw[d], acc);
        }
        ob[(size_t)c * HWn] = acc;
    }
}

// ---------------- launch ----------------
extern "C" void kernel_launch(void* const* d_in, const int* in_sizes, int n_in,
                              void* d_out, int out_size) {
    const float* x  = (const float*)d_in[0];   // windowed_x [2,31,7,192,192]
    const float* gw = (const float*)d_in[1];   // gen_w [70,31,3,3]
    const float* gb = (const float*)d_in[2];   // gen_b [70]
    float* out = (float*)d_out;                // [2,31,192,192]

    cudaFuncSetAttribute(conv_kernel, cudaFuncAttributeMaxDynamicSharedMemorySize, CONV_SMEM_BYTES);
    cudaFuncSetAttribute(kan_kernel,  cudaFuncAttributeMaxDynamicSharedMemorySize, KAN_SMEM_BYTES);

    mean_kernel<<<(Bn * Cn * HWn / 8) / 256, 256>>>(x);
    conv_kernel<<<dim3(Wn / TILE_W, Hn / TILE_H, Bn * 7), 256, CONV_SMEM_BYTES>>>(gw, gb);
    kan_kernel<<<dim3(HWn / 256, Bn), 256, KAN_SMEM_BYTES>>>(x, out);
}

// round 6
// speedup vs baseline: 1.4123x; 1.0595x over previous
#include <cuda_runtime.h>
#include <cuda_bf16.h>
#include <cstdint>

#define Bn 2
#define Cn 31
#define Dn 7
#define Hn 192
#define Wn 192
#define HWn (Hn * Wn)          // 36864
#define KP 70                  // KAN_PARAMS
#define COEF_LEN 56
#define NB 8                   // N_BASIS

// ---------------- scratch (no allocations allowed) ----------------
__device__ float g_ctx[Bn * Cn * HWn];   // [B, C, H, W]   ~9.1 MB
__device__ float g_wts[Bn * KP * HWn];   // [B, 70, H, W]  ~20.6 MB

// ---------------- packed f32x2 helpers (sm_103a FFMA2) ----------------
__device__ __forceinline__ unsigned long long fma2(unsigned long long a,
                                                   unsigned long long b,
                                                   unsigned long long c) {
    unsigned long long d;
    asm("fma.rn.f32x2 %0, %1, %2, %3;" : "=l"(d) : "l"(a), "l"(b), "l"(c));
    return d;
}
__device__ __forceinline__ unsigned long long pack2(float lo, float hi) {
    unsigned long long d;
    asm("mov.b64 %0, {%1, %2};" : "=l"(d) : "f"(lo), "f"(hi));
    return d;
}
__device__ __forceinline__ void unpack2(unsigned long long v, float& lo, float& hi) {
    asm("mov.b64 {%0, %1}, %2;" : "=f"(lo), "=f"(hi) : "l"(v));
}

// ---------------- kernel 1: mean over D (float4, round-3 form) ----------------
__global__ void mean_kernel(const float* __restrict__ x) {
    int i = blockIdx.x * 256 + threadIdx.x;        // float4 index
    const int HW4 = HWn / 4;                       // 9216
    int hw4 = i % HW4;
    int bc  = i / HW4;
    const float4* p = (const float4*)(x + (size_t)bc * Dn * HWn) + hw4;
    float4 s = make_float4(0.f, 0.f, 0.f, 0.f);
#pragma unroll
    for (int d = 0; d < Dn; d++) {
        float4 v = p[(size_t)d * HW4];
        s.x += v.x; s.y += v.y; s.z += v.z; s.w += v.w;
    }
    const float inv7 = 1.0f / 7.0f;
    s.x *= inv7; s.y *= inv7; s.z *= inv7; s.w *= inv7;
    ((float4*)g_ctx)[i] = s;
}

// ---------------- kernel 2: 3x3 SAME conv 31->70 + bias (f32x2, round-3 form) ----------------
#define TILE_W 64
#define TILE_H 16
#define TC 10
#define CI_CHUNK 16
#define S_TILE_FLOATS (CI_CHUNK * 18 * 66)          // 19008 floats = 76032 B
#define S_W_PAIRS     (Cn * 9 * TC)                 // 2790 pairs   = 22320 B
#define CONV_SMEM_BYTES (S_TILE_FLOATS * 4 + S_W_PAIRS * 8)

__global__ void __launch_bounds__(256, 2)
conv_kernel(const float* __restrict__ gw, const float* __restrict__ gb) {
    extern __shared__ char smem_raw[];
    float* s_tile = (float*)smem_raw;                                    // [ci_chunk][18][66]
    unsigned long long* s_wd = (unsigned long long*)(smem_raw + S_TILE_FLOATS * 4);

    int tid = threadIdx.x;
    int bz = blockIdx.z;
    int cochunk = bz % 7;
    int b = bz / 7;

    int ox = blockIdx.x * TILE_W - 1;
    int oy = blockIdx.y * TILE_H - 1;
    const float* ctx = g_ctx + (size_t)b * Cn * HWn;

    // stage duplicated weight pairs for this cout chunk (once)
    for (int idx = tid; idx < S_W_PAIRS; idx += 256) {
        int j = idx % TC;
        int r = idx / TC;                 // ci*9 + kk
        int ci = r / 9, kk = r % 9;
        int co = cochunk * TC + j;
        float w = gw[((size_t)co * Cn + ci) * 9 + kk];
        s_wd[idx] = pack2(w, w);
    }

    int lx = (tid & 31) * 2;              // 0..62
    int ly = (tid >> 5) * 2;              // 0..14

    unsigned long long acc[2][TC];
#pragma unroll
    for (int p = 0; p < 2; p++)
#pragma unroll
        for (int j = 0; j < TC; j++) acc[p][j] = 0ull;

    for (int c0 = 0; c0 < Cn; c0 += CI_CHUNK) {
        int nc = (Cn - c0 < CI_CHUNK) ? (Cn - c0) : CI_CHUNK;
        // stage input tile chunk (with halo, zero-padded)
        for (int idx = tid; idx < nc * 18 * 66; idx += 256) {
            int ci = idx / (18 * 66);
            int r  = idx % (18 * 66);
            int y = r / 66, xx = r % 66;
            int gy = oy + y, gx = ox + xx;
            float v = 0.f;
            if (gy >= 0 && gy < Hn && gx >= 0 && gx < Wn)
                v = ctx[(size_t)(c0 + ci) * HWn + gy * Wn + gx];
            s_tile[idx] = v;
        }
        __syncthreads();

#pragma unroll 1
        for (int cl = 0; cl < nc; cl++) {
            const float* t = s_tile + cl * (18 * 66);
            int ci_g = c0 + cl;

#pragma unroll
            for (int ky = 0; ky < 3; ky++) {
                float2 a0 = *(const float2*)(t + (ly + ky) * 66 + lx);
                float2 a1 = *(const float2*)(t + (ly + ky) * 66 + lx + 2);
                float2 b0 = *(const float2*)(t + (ly + ky + 1) * 66 + lx);
                float2 b1 = *(const float2*)(t + (ly + ky + 1) * 66 + lx + 2);
                unsigned long long pa[3], pb[3];
                pa[0] = pack2(a0.x, a0.y); pa[1] = pack2(a0.y, a1.x); pa[2] = pack2(a1.x, a1.y);
                pb[0] = pack2(b0.x, b0.y); pb[1] = pack2(b0.y, b1.x); pb[2] = pack2(b1.x, b1.y);

#pragma unroll
                for (int kx = 0; kx < 3; kx++) {
                    const ulonglong2* wrow =
                        (const ulonglong2*)(s_wd + (size_t)(ci_g * 9 + ky * 3 + kx) * TC);
                    ulonglong2 w01 = wrow[0];
                    ulonglong2 w23 = wrow[1];
                    ulonglong2 w45 = wrow[2];
                    ulonglong2 w67 = wrow[3];
                    ulonglong2 w89 = wrow[4];
                    unsigned long long wv[TC] = {w01.x, w01.y, w23.x, w23.y, w45.x,
                                                 w45.y, w67.x, w67.y, w89.x, w89.y};
#pragma unroll
                    for (int j = 0; j < TC; j++) {
                        acc[0][j] = fma2(pa[kx], wv[j], acc[0][j]);
                        acc[1][j] = fma2(pb[kx], wv[j], acc[1][j]);
                    }
                }
            }
        }
        __syncthreads();
    }

    int gx = blockIdx.x * TILE_W + lx;
    float* outp = g_wts + (size_t)b * KP * HWn;
#pragma unroll
    for (int j = 0; j < TC; j++) {
        int co = cochunk * TC + j;
        float bias = __ldg(gb + co);
#pragma unroll
        for (int p = 0; p < 2; p++) {
            int gy = blockIdx.y * TILE_H + ly + p;
            float lo, hi;
            unpack2(acc[p][j], lo, hi);
            *(float2*)(outp + (size_t)co * HWn + gy * Wn + gx) =
                make_float2(lo + bias, hi + bias);
        }
    }
}

// ---------------- kernel 3: fused bspline + silu, 4-channel batched loads ----------------
// Change vs round 3: x loads are issued 4 channels at a time (28 independent LDGs
// front-loaded) -> MLP 7 -> 28 per warp, lifting DRAM-latency-bound streaming to full BW.
#define KAN_ROW 99
#define KAN_SMEM_BYTES (256 * KAN_ROW * 4)

__global__ void __launch_bounds__(256, 2)
kan_kernel(const float* __restrict__ xin, float* __restrict__ out) {
    extern __shared__ float smem[];
    int tid = threadIdx.x;
    int b = blockIdx.y;
    int p = blockIdx.x * 256 + tid;

    float* ws = smem + tid * KAN_ROW;
    const float* wbase = g_wts + (size_t)b * KP * HWn + p;

    // zero pads (3 each side of the 8 real coefficients per d)
#pragma unroll
    for (int d = 0; d < Dn; d++) {
        ws[d * 14 + 0]  = 0.f; ws[d * 14 + 1]  = 0.f; ws[d * 14 + 2]  = 0.f;
        ws[d * 14 + 11] = 0.f; ws[d * 14 + 12] = 0.f; ws[d * 14 + 13] = 0.f;
    }
#pragma unroll
    for (int k = 0; k < COEF_LEN; k++) {
        int d = k >> 3, g = k & 7;
        ws[d * 14 + 3 + g] = wbase[(size_t)k * HWn];
    }

    float uw[Dn], rw[Dn];
#pragma unroll
    for (int d = 0; d < Dn; d++) {
        uw[d] = wbase[(size_t)(COEF_LEN + d) * HWn] * (1.0f / 6.0f);  // fold spline 1/6
        rw[d] = wbase[(size_t)(COEF_LEN + Dn + d) * HWn];
    }

    const float* xb = xin + (size_t)b * Cn * Dn * HWn + p;
    float* ob = out + (size_t)b * Cn * HWn + p;

#pragma unroll 1
    for (int c0 = 0; c0 < Cn; c0 += 4) {
        // ---- batched load phase: up to 28 independent LDGs in flight ----
        float xv[4][Dn];
#pragma unroll
        for (int cc = 0; cc < 4; cc++) {
            if (c0 + cc < Cn) {
#pragma unroll
                for (int d = 0; d < Dn; d++)
                    xv[cc][d] = xb[(size_t)((c0 + cc) * Dn + d) * HWn];
            }
        }
        // ---- compute phase ----
#pragma unroll
        for (int cc = 0; cc < 4; cc++) {
            if (c0 + cc < Cn) {
                float acc = 0.f;
#pragma unroll
                for (int d = 0; d < Dn; d++) {
                    float x = xv[cc][d];
                    // uniform cubic B-spline on knots -2.2 + 0.4k; 11 valid intervals
                    float xs = fmaf(x, 2.5f, 5.5f);
                    float jf = floorf(xs);
                    int j = (int)jf;
                    float t = xs - jf;
                    unsigned ju = (unsigned)j;
                    float vm = (ju <= 10u) ? 1.f : 0.f;
                    int jc = (ju <= 10u) ? j : 0;

                    float t2 = t * t;
                    float t3 = t2 * t;
                    float omt = 1.f - t;
                    float u0 = omt * omt * omt;                   // 1/6 folded into uw
                    float u1 = 3.f * t3 - 6.f * t2 + 4.f;
                    float u2 = -3.f * t3 + 3.f * t2 + 3.f * t + 1.f;
                    float u3 = t3;

                    const float* cf = ws + d * 14 + jc;
                    float sa = u0 * cf[0];
                    sa = fmaf(u1, cf[1], sa);
                    sa = fmaf(u2, cf[2], sa);
                    sa = fmaf(u3, cf[3], sa);
                    acc = fmaf(sa * vm, uw[d], acc);

                    float sig = 1.f / (1.f + __expf(-x));
                    acc = fmaf(x * sig, rw[d], acc);
                }
                ob[(size_t)(c0 + cc) * HWn] = acc;
            }
        }
    }
}

// ---------------- launch ----------------
extern "C" void kernel_launch(void* const* d_in, const int* in_sizes, int n_in,
                              void* d_out, int out_size) {
    const float* x  = (const float*)d_in[0];   // windowed_x [2,31,7,192,192]
    const float* gw = (const float*)d_in[1];   // gen_w [70,31,3,3]
    const float* gb = (const float*)d_in[2];   // gen_b [70]
    float* out = (float*)d_out;                // [2,31,192,192]

    cudaFuncSetAttribute(conv_kernel, cudaFuncAttributeMaxDynamicSharedMemorySize, CONV_SMEM_BYTES);
    cudaFuncSetAttribute(kan_kernel,  cudaFuncAttributeMaxDynamicSharedMemorySize, KAN_SMEM_BYTES);

    mean_kernel<<<(Bn * Cn * HWn / 4) / 256, 256>>>(x);
    conv_kernel<<<dim3(Wn / TILE_W, Hn / TILE_H, Bn * 7), 256, CONV_SMEM_BYTES>>>(gw, gb);
    kan_kernel<<<dim3(HWn / 256, Bn), 256, KAN_SMEM_BYTES>>>(x, out);
}